// round 9
// baseline (speedup 1.0000x reference)
#include <cuda_runtime.h>
#include <stdint.h>
#include <math.h>

#define BATCH 1024
#define DIM   128
#define N0    25
#define N1    10
#define NPB   250
#define FUSE_BLOCKS 32          // 32 blocks x 8 rows = 256 product rows

// g_act[b][0:128)=h0, [128:256)=mean idx1, [256:384)=mean leaf
__device__ __align__(16) float g_act[BATCH * 384];
// g_Wf rows 0..127 = W0a ; rows 128..383 = W1 @ W0b
__device__ __align__(16) float g_Wf[384 * 128];

__device__ __forceinline__ void cp_async16(uint32_t saddr, const void* gptr) {
    asm volatile("cp.async.cg.shared.global [%0], [%1], 16;" :: "r"(saddr), "l"(gptr));
}
__device__ __forceinline__ void cp_commit() {
    asm volatile("cp.async.commit_group;");
}
template <int N>
__device__ __forceinline__ void cp_wait() {
    asm volatile("cp.async.wait_group %0;" :: "n"(N));
}

// ---------------------------------------------------------------------------
// Kernel A: blocks 0..1023 gather+reduce; blocks 1024.. build fused weights.
// 256 threads. (round-4 proven version, unchanged)
// ---------------------------------------------------------------------------
__global__ __launch_bounds__(256) void gather_fuse_kernel(
    const float* __restrict__ embed,
    const float* __restrict__ W0,
    const float* __restrict__ W1,
    const int*   __restrict__ roots,
    const int*   __restrict__ idx1,
    const int*   __restrict__ idx2)
{
    __shared__ int   sIdx2[NPB];
    __shared__ int   sIdx1[N0];
    __shared__ __align__(16) float sRedA[8 * 128];
    __shared__ __align__(16) float sRedB[8 * 128];
    __shared__ __align__(16) float sW1[8 * 128];
    __shared__ __align__(16) float sRedF[2 * 8 * 128];

    const int tid = threadIdx.x;

    if (blockIdx.x < BATCH) {
        const int b = blockIdx.x;
        const int w = tid >> 5;
        const int l = tid & 31;
        const int e = l * 4;

        if (tid < NPB) sIdx2[tid] = idx2[b * NPB + tid];
        if (tid < N0)  sIdx1[tid] = idx1[b * N0 + tid];
        __syncthreads();

        const float* E = embed + e;

        float4 a2 = make_float4(0.f, 0.f, 0.f, 0.f);
        int r = w;
        for (; r + 24 < NPB; r += 32) {
            const float4 v0 = *(const float4*)(E + (size_t)sIdx2[r     ] * DIM);
            const float4 v1 = *(const float4*)(E + (size_t)sIdx2[r +  8] * DIM);
            const float4 v2 = *(const float4*)(E + (size_t)sIdx2[r + 16] * DIM);
            const float4 v3 = *(const float4*)(E + (size_t)sIdx2[r + 24] * DIM);
            a2.x += (v0.x + v1.x) + (v2.x + v3.x);
            a2.y += (v0.y + v1.y) + (v2.y + v3.y);
            a2.z += (v0.z + v1.z) + (v2.z + v3.z);
            a2.w += (v0.w + v1.w) + (v2.w + v3.w);
        }
        for (; r < NPB; r += 8) {
            const float4 v = *(const float4*)(E + (size_t)sIdx2[r] * DIM);
            a2.x += v.x; a2.y += v.y; a2.z += v.z; a2.w += v.w;
        }

        float4 a1 = make_float4(0.f, 0.f, 0.f, 0.f);
        for (int q = w; q < N0; q += 8) {
            const float4 v = *(const float4*)(E + (size_t)sIdx1[q] * DIM);
            a1.x += v.x; a1.y += v.y; a1.z += v.z; a1.w += v.w;
        }

        if (w == 0) {
            const float4 h0 = *(const float4*)(E + (size_t)__ldg(&roots[b]) * DIM);
            *(float4*)&g_act[b * 384 + e] = h0;
        }

        *(float4*)&sRedA[w * 128 + e] = a2;
        *(float4*)&sRedB[w * 128 + e] = a1;
        __syncthreads();

        if (tid < 128) {
            float s = 0.f;
#pragma unroll
            for (int j = 0; j < 8; j++) s += sRedB[j * 128 + tid];
            g_act[b * 384 + 128 + tid] = s * (1.0f / 25.0f);
        } else {
            const int dd = tid - 128;
            float s = 0.f;
#pragma unroll
            for (int j = 0; j < 8; j++) s += sRedA[j * 128 + dd];
            g_act[b * 384 + 256 + dd] = s * (1.0f / 250.0f);
        }
    } else {
        const int fb  = blockIdx.x - BATCH;
        const int kk0 = fb * 8;

        {
            const int base = fb * 512;
#pragma unroll
            for (int i = 0; i < 2; i++)
                g_Wf[base + tid + i * 256] = __ldg(&W0[base + tid + i * 256]);
        }

        for (int i = tid; i < 1024; i += 256)
            sW1[i] = __ldg(&W1[kk0 * 128 + i]);
        __syncthreads();

        const int g = tid >> 7;
        const int d = tid & 127;

        float acc[8];
#pragma unroll
        for (int rr = 0; rr < 8; rr++) acc[rr] = 0.f;

        const int jbeg = g * 64;
        for (int j = 0; j < 64; j += 4) {
            float wv[4];
#pragma unroll
            for (int u = 0; u < 4; u++)
                wv[u] = __ldg(&W0[(size_t)(128 + jbeg + j + u) * 128 + d]);
#pragma unroll
            for (int u = 0; u < 4; u++) {
#pragma unroll
                for (int rr = 0; rr < 8; rr++)
                    acc[rr] = fmaf(sW1[rr * 128 + jbeg + j + u], wv[u], acc[rr]);
            }
        }

#pragma unroll
        for (int rr = 0; rr < 8; rr++)
            sRedF[g * 1024 + rr * 128 + d] = acc[rr];
        __syncthreads();

        if (g == 0) {
#pragma unroll
            for (int rr = 0; rr < 8; rr++)
                g_Wf[(size_t)(128 + kk0 + rr) * 128 + d] =
                    sRedF[rr * 128 + d] + sRedF[1024 + rr * 128 + d];
        }
    }
}

// ---------------------------------------------------------------------------
// Kernel B: out = sigmoid(g_act @ g_Wf + b0).
// grid=128, block=512, 8 rows/block.
// d = tid&127 (output col), rg = tid>>7 (4 row-groups x 2 rows).
// Each thread owns 2 complete outputs over full k=384 — no reduction.
// Weights stream through a 4-stage cp.async ring (16 k per chunk).
// ---------------------------------------------------------------------------
#define KCH   16
#define NCH   (384 / KCH)            // 24 chunks
#define CHF   (KCH * 128)            // 2048 floats per chunk
#define STAGES 4

__global__ __launch_bounds__(512) void mlp_kernel(
    const float* __restrict__ b0,
    float*       __restrict__ out)
{
    __shared__ __align__(16) float sActT[384 * 8];          // [k][r], 12 KB
    __shared__ __align__(16) float sW[STAGES][CHF];          // 4 x 8 KB

    const int tid  = threadIdx.x;
    const int d    = tid & 127;
    const int rg   = tid >> 7;           // 0..3
    const int row0 = blockIdx.x * 8;

    const uint32_t swBase = (uint32_t)__cvta_generic_to_shared(&sW[0][0]);

    // Prologue: issue chunks 0..2 into stages 0..2 (one 16B quad per thread each)
#pragma unroll
    for (int c = 0; c < STAGES - 1; c++) {
        const uint32_t dst = swBase + (uint32_t)c * (CHF * 4);
        cp_async16(dst + tid * 16, g_Wf + (size_t)c * CHF + tid * 4);
        cp_commit();
    }

    // Stage transposed activations for 8 rows (overlaps with prologue copies)
    for (int i = tid; i < 8 * 384; i += 512) {
        const int r = i / 384;
        const int k = i - r * 384;
        sActT[k * 8 + r] = g_act[(size_t)(row0 + r) * 384 + k];
    }

    float acc0 = 0.f, acc1 = 0.f;

    for (int c = 0; c < NCH; c++) {
        cp_wait<STAGES - 2>();   // chunk c complete (2 groups may stay in flight)
        __syncthreads();          // chunk c visible block-wide; also guards sActT
                                  // and proves compute(c-1) done before refill below

        // issue chunk c+3 into stage (c+3)%4; always commit to keep group count fixed
        const int cn = c + STAGES - 1;
        if (cn < NCH) {
            const uint32_t dst = swBase + (uint32_t)(cn & (STAGES - 1)) * (CHF * 4);
            cp_async16(dst + tid * 16, g_Wf + (size_t)cn * CHF + tid * 4);
        }
        cp_commit();

        const float* W = sW[c & (STAGES - 1)];
#pragma unroll
        for (int kl = 0; kl < KCH; kl++) {
            const int k = c * KCH + kl;
            const float w = W[kl * 128 + d];
            const float2 a = *(const float2*)&sActT[k * 8 + rg * 2];
            acc0 = fmaf(a.x, w, acc0);
            acc1 = fmaf(a.y, w, acc1);
        }
    }

    const float bb = __ldg(&b0[d]);
    const int rbase = row0 + rg * 2;
    out[(size_t)(rbase    ) * 128 + d] = 1.0f / (1.0f + __expf(-(acc0 + bb)));
    out[(size_t)(rbase + 1) * 128 + d] = 1.0f / (1.0f + __expf(-(acc1 + bb)));
}

// ---------------------------------------------------------------------------
// Inputs: embed_table, W0, b0, W1, roots, idx1, idx2
// ---------------------------------------------------------------------------
extern "C" void kernel_launch(void* const* d_in, const int* in_sizes, int n_in,
                              void* d_out, int out_size)
{
    const float* embed = (const float*)d_in[0];
    const float* W0    = (const float*)d_in[1];
    const float* b0    = (const float*)d_in[2];
    const float* W1    = (const float*)d_in[3];
    const int*   roots = (const int*)  d_in[4];
    const int*   idx1  = (const int*)  d_in[5];
    const int*   idx2  = (const int*)  d_in[6];
    float*       out   = (float*)d_out;

    gather_fuse_kernel<<<BATCH + FUSE_BLOCKS, 256>>>(embed, W0, W1, roots, idx1, idx2);
    mlp_kernel<<<BATCH / 8, 512>>>(b0, out);
}

// round 11
// speedup vs baseline: 1.2145x; 1.2145x over previous
#include <cuda_runtime.h>
#include <stdint.h>
#include <math.h>

#define BATCH 1024
#define DIM   128
#define N0    25
#define N1    10
#define NPB   250
#define FUSE_BLOCKS 32           // blocks 0..31 build g_Wf (8 product rows each)
#define GATHER_BLOCKS (BATCH / 2)
#define FUSE_DONE FUSE_BLOCKS

// Fused weight: rows 0..127 = W0[0:128,:] ; rows 128..383 = W1 @ W0[128:256,:]
__device__ __align__(16) float g_Wf[384 * 128];
__device__ int g_flag;          // zero-init; monotonic across replays (benign: Wf replay-invariant)

// ---------------------------------------------------------------------------
// Single kernel. Blocks 0..31: fuse weights, release flag.
// Blocks 32..543: gather+reduce 2 batch rows -> smem act -> acquire flag ->
// dual matvec vs g_Wf (L2/L1) -> sigmoid -> out. 256 threads.
// ---------------------------------------------------------------------------
__global__ __launch_bounds__(256) void graphsage_kernel(
    const float* __restrict__ embed,
    const float* __restrict__ W0,
    const float* __restrict__ b0,
    const float* __restrict__ W1,
    const int*   __restrict__ roots,
    const int*   __restrict__ idx1,
    const int*   __restrict__ idx2,
    float*       __restrict__ out)
{
    const int tid = threadIdx.x;

    if (blockIdx.x < FUSE_BLOCKS) {
        // ------------------ fuse path (proven round-4 form) ------------------
        __shared__ __align__(16) float sW1[8 * 128];
        __shared__ __align__(16) float sRedF[2 * 8 * 128];

        const int fb  = blockIdx.x;
        const int kk0 = fb * 8;

        {   // copy W0a rows (4 rows per block)
            const int base = fb * 512;
#pragma unroll
            for (int i = 0; i < 2; i++)
                g_Wf[base + tid + i * 256] = __ldg(&W0[base + tid + i * 256]);
        }

        for (int i = tid; i < 1024; i += 256)
            sW1[i] = __ldg(&W1[kk0 * 128 + i]);
        __syncthreads();

        const int g = tid >> 7;
        const int d = tid & 127;

        float acc[8];
#pragma unroll
        for (int rr = 0; rr < 8; rr++) acc[rr] = 0.f;

        const int jbeg = g * 64;
        for (int j = 0; j < 64; j += 4) {
            float wv[4];
#pragma unroll
            for (int u = 0; u < 4; u++)
                wv[u] = __ldg(&W0[(size_t)(128 + jbeg + j + u) * 128 + d]);
#pragma unroll
            for (int u = 0; u < 4; u++) {
#pragma unroll
                for (int rr = 0; rr < 8; rr++)
                    acc[rr] = fmaf(sW1[rr * 128 + jbeg + j + u], wv[u], acc[rr]);
            }
        }

#pragma unroll
        for (int rr = 0; rr < 8; rr++)
            sRedF[g * 1024 + rr * 128 + d] = acc[rr];
        __syncthreads();

        if (g == 0) {
#pragma unroll
            for (int rr = 0; rr < 8; rr++)
                g_Wf[(size_t)(128 + kk0 + rr) * 128 + d] =
                    sRedF[rr * 128 + d] + sRedF[1024 + rr * 128 + d];
        }
        __threadfence();          // release: Wf rows visible before flag bump
        __syncthreads();
        if (tid == 0) atomicAdd(&g_flag, 1);
        return;
    }

    // ------------------ gather + per-block MLP ------------------
    __shared__ int   sIdx2[2 * NPB];
    __shared__ int   sIdx1[2 * N0];
    __shared__ __align__(16) float sRedA[2 * 4 * 128];   // leaf partials
    __shared__ __align__(16) float sRedB[2 * 4 * 128];   // idx1 partials
    __shared__ __align__(16) float sAct[2 * 384];         // [h0|mean1|mean2] x2

    const int gb  = blockIdx.x - FUSE_BLOCKS;   // 0..511
    const int b0r = gb * 2;                      // first batch row

    const int w  = tid >> 5;        // warp 0..7
    const int l  = tid & 31;        // lane
    const int be = w >> 2;          // batch element 0/1
    const int wl = w & 3;           // warp index within element
    const int e  = l * 4;           // float4 offset in 128-dim row

    // FIX: strided staging loops (2*NPB = 500 > blockDim)
    for (int i = tid; i < 2 * NPB; i += 256) sIdx2[i] = idx2[b0r * NPB + i];
    if (tid < 2 * N0) sIdx1[tid] = idx1[b0r * N0 + tid];
    __syncthreads();

    const float* E = embed + e;
    const int* myIdx2 = sIdx2 + be * NPB;
    const int* myIdx1 = sIdx1 + be * N0;

    // leaf rows: warp handles r = wl, wl+4, ... (4-deep unroll)
    float4 a2 = make_float4(0.f, 0.f, 0.f, 0.f);
    int r = wl;
    for (; r + 12 < NPB; r += 16) {
        const float4 v0 = *(const float4*)(E + (size_t)myIdx2[r     ] * DIM);
        const float4 v1 = *(const float4*)(E + (size_t)myIdx2[r +  4] * DIM);
        const float4 v2 = *(const float4*)(E + (size_t)myIdx2[r +  8] * DIM);
        const float4 v3 = *(const float4*)(E + (size_t)myIdx2[r + 12] * DIM);
        a2.x += (v0.x + v1.x) + (v2.x + v3.x);
        a2.y += (v0.y + v1.y) + (v2.y + v3.y);
        a2.z += (v0.z + v1.z) + (v2.z + v3.z);
        a2.w += (v0.w + v1.w) + (v2.w + v3.w);
    }
    for (; r < NPB; r += 4) {
        const float4 v = *(const float4*)(E + (size_t)myIdx2[r] * DIM);
        a2.x += v.x; a2.y += v.y; a2.z += v.z; a2.w += v.w;
    }

    // idx1 rows
    float4 a1 = make_float4(0.f, 0.f, 0.f, 0.f);
    for (int q = wl; q < N0; q += 4) {
        const float4 v = *(const float4*)(E + (size_t)myIdx1[q] * DIM);
        a1.x += v.x; a1.y += v.y; a1.z += v.z; a1.w += v.w;
    }

    // root embedding straight into sAct
    if (wl == 0) {
        const float4 h0 = *(const float4*)(E + (size_t)__ldg(&roots[b0r + be]) * DIM);
        *(float4*)&sAct[be * 384 + e] = h0;
    }

    *(float4*)&sRedA[(be * 4 + wl) * 128 + e] = a2;
    *(float4*)&sRedB[(be * 4 + wl) * 128 + e] = a1;
    __syncthreads();

    // finish means: 256 threads cover 2 elements x 128 dims
    {
        const int mb = tid >> 7;          // element
        const int dd = tid & 127;
        float s1 = 0.f, s2 = 0.f;
#pragma unroll
        for (int j = 0; j < 4; j++) {
            s1 += sRedB[(mb * 4 + j) * 128 + dd];
            s2 += sRedA[(mb * 4 + j) * 128 + dd];
        }
        sAct[mb * 384 + 128 + dd] = s1 * (1.0f / 25.0f);
        sAct[mb * 384 + 256 + dd] = s2 * (1.0f / 250.0f);
    }

    // acquire fused weights (fuse blocks are wave-1; typically zero wait)
    if (tid == 0) {
        while (atomicAdd(&g_flag, 0) < FUSE_DONE) {}
        __threadfence();          // acquire: order flag observation before Wf reads
    }
    __syncthreads();

    // ------------------ per-block MLP: 2 rows x 128 cols ------------------
    {
        const int d  = tid & 127;
        const int mb = tid >> 7;
        const float* A = &sAct[mb * 384];

        float acc = 0.f;
        for (int k0 = 0; k0 < 384; k0 += 8) {
            float wv[8];
#pragma unroll
            for (int u = 0; u < 8; u++)
                wv[u] = __ldg(&g_Wf[(size_t)(k0 + u) * 128 + d]);
#pragma unroll
            for (int u = 0; u < 8; u++)
                acc = fmaf(A[k0 + u], wv[u], acc);
        }

        const float x = acc + __ldg(&b0[d]);
        out[(size_t)(b0r + mb) * 128 + d] = 1.0f / (1.0f + __expf(-x));
    }
}

// ---------------------------------------------------------------------------
// Inputs: embed_table, W0, b0, W1, roots, idx1, idx2
// ---------------------------------------------------------------------------
extern "C" void kernel_launch(void* const* d_in, const int* in_sizes, int n_in,
                              void* d_out, int out_size)
{
    const float* embed = (const float*)d_in[0];
    const float* W0    = (const float*)d_in[1];
    const float* b0    = (const float*)d_in[2];
    const float* W1    = (const float*)d_in[3];
    const int*   roots = (const int*)  d_in[4];
    const int*   idx1  = (const int*)  d_in[5];
    const int*   idx2  = (const int*)  d_in[6];
    float*       out   = (float*)d_out;

    graphsage_kernel<<<FUSE_BLOCKS + GATHER_BLOCKS, 256>>>(
        embed, W0, b0, W1, roots, idx1, idx2, out);
}